// round 16
// baseline (speedup 1.0000x reference)
#include <cuda_runtime.h>

// 64-thread CTA, 1 sample, ~24 CTAs/SM: maximize CTA-level phase mixing.
//   h = relu(x[b,:] @ w1[b,:,:] + b1[b,:])   (D=128 -> H=256)
//   out = h @ w2[b,:,:] + b2[b,:]            (H=256 -> C=64)
// w2 rows with h[j]==0 are never loaded (exact, ~50% skipped).
// R12 proved sparse loads only stream fast when blended with other CTAs'
// dense traffic on the same SM. With ~24 resident CTAs at independent
// phase offsets, ~75% are always in the dense phase -> SM aggregate DRAM
// demand stays dense-dominated through every sparse phase.
// Also: GEMV1 is reduction-free (thread owns 4 h-cols over full D), one
// fewer barrier; GEMV2 uses the proven register-mask predication (R13),
// now 64 slots/thread (~32 active loads, deepest sparse stream yet).

#define B_DIM 4096
#define D_DIM 128
#define H_DIM 256
#define C_DIM 64

__global__ void __launch_bounds__(64, 24) mlp_64t_kernel(
    const float* __restrict__ x,
    const float* __restrict__ w1,
    const float* __restrict__ b1,
    const float* __restrict__ w2,
    const float* __restrict__ b2,
    float* __restrict__ out)
{
    const int l = threadIdx.x;       // 0..63
    const int b = blockIdx.x;

    __shared__ float  x_s[D_DIM];    // 512 B
    __shared__ float  h_s[H_DIM];    // 1 KB
    __shared__ float4 part[64];      // 1 KB

    // ---- stage x[b,:]: 64 threads x float2 ----
    reinterpret_cast<float2*>(x_s)[l] =
        reinterpret_cast<const float2*>(x + (size_t)b * D_DIM)[l];
    __syncthreads();

    // ========== GEMV1 (reduction-free): thread l owns h cols 4l..4l+3 =====
    // w1[b] as float4[128][64]; two warps cover each 1KB row -> coalesced.
    // 128 float4 LDGs/thread, full-D register accumulation, no cross-thread
    // reduction, bias+ReLU in-register.
    {
        const float4* w1v = reinterpret_cast<const float4*>(
            w1 + (size_t)b * D_DIM * H_DIM);

        float4 acc = make_float4(0.f, 0.f, 0.f, 0.f);
        #pragma unroll 16
        for (int d = 0; d < D_DIM; ++d) {
            const float  xv = x_s[d];
            const float4 w  = __ldcs(&w1v[d * (H_DIM / 4) + l]);
            acc.x = fmaf(xv, w.x, acc.x);
            acc.y = fmaf(xv, w.y, acc.y);
            acc.z = fmaf(xv, w.z, acc.z);
            acc.w = fmaf(xv, w.w, acc.w);
        }
        const float4 bb = reinterpret_cast<const float4*>(
            b1 + (size_t)b * H_DIM)[l];
        float4 h4;
        h4.x = fmaxf(acc.x + bb.x, 0.f);
        h4.y = fmaxf(acc.y + bb.y, 0.f);
        h4.z = fmaxf(acc.z + bb.z, 0.f);
        h4.w = fmaxf(acc.w + bb.w, 0.f);
        reinterpret_cast<float4*>(h_s)[l] = h4;
    }
    __syncthreads();

    // ========== GEMV2 (sparse, register-mask predication): =================
    // out[c] = sum_{j: h[j]>0} h[j] * w2[j, c]
    // w2[b] as float4[256][16]. Thread: (jslot = l>>4 in 0..3, cg = l&15).
    // Row j = jslot + 4*i (affine), 64 slots/thread, masks in 2 registers.
    // 16-lane groups share j -> predicated-off LDG is divergence-free.
    {
        const float4* w2v = reinterpret_cast<const float4*>(
            w2 + (size_t)b * H_DIM * C_DIM);
        const int cg    = l & 15;
        const int jslot = l >> 4;

        // Phase 1: build 64-bit activity mask (independent pipelined LDS).
        unsigned mLo = 0, mHi = 0;
        #pragma unroll
        for (int i = 0; i < 32; ++i) {
            mLo |= (h_s[jslot + 4 * i]        > 0.f) ? (1u << i) : 0u;
            mHi |= (h_s[jslot + 4 * (i + 32)] > 0.f) ? (1u << i) : 0u;
        }

        // Phase 2: predicated loads from register bits only -> batch freely.
        float4 acc = make_float4(0.f, 0.f, 0.f, 0.f);
        #pragma unroll 8
        for (int i = 0; i < 32; ++i) {
            if ((mLo >> i) & 1u) {
                const int j = jslot + 4 * i;
                const float4 wv = __ldcs(&w2v[j * (C_DIM / 4) + cg]);
                const float  hv = h_s[j];
                acc.x = fmaf(hv, wv.x, acc.x);
                acc.y = fmaf(hv, wv.y, acc.y);
                acc.z = fmaf(hv, wv.z, acc.z);
                acc.w = fmaf(hv, wv.w, acc.w);
            }
            if ((mHi >> i) & 1u) {
                const int j = jslot + 4 * (i + 32);
                const float4 wv = __ldcs(&w2v[j * (C_DIM / 4) + cg]);
                const float  hv = h_s[j];
                acc.x = fmaf(hv, wv.x, acc.x);
                acc.y = fmaf(hv, wv.y, acc.y);
                acc.z = fmaf(hv, wv.z, acc.z);
                acc.w = fmaf(hv, wv.w, acc.w);
            }
        }
        part[l] = acc;   // index = jslot*16 + cg
    }
    __syncthreads();

    // reduce 4 jslot-partials per cg, add bias, streaming store
    if (l < 16) {
        float4 p0 = part[l];
        float4 p1 = part[16 + l];
        float4 p2 = part[32 + l];
        float4 p3 = part[48 + l];
        float4 bb = reinterpret_cast<const float4*>(b2 + (size_t)b * C_DIM)[l];
        float4 o;
        o.x = (p0.x + p1.x) + (p2.x + p3.x) + bb.x;
        o.y = (p0.y + p1.y) + (p2.y + p3.y) + bb.y;
        o.z = (p0.z + p1.z) + (p2.z + p3.z) + bb.z;
        o.w = (p0.w + p1.w) + (p2.w + p3.w) + bb.w;
        __stcs(reinterpret_cast<float4*>(out + (size_t)b * C_DIM) + l, o);
    }
}

extern "C" void kernel_launch(void* const* d_in, const int* in_sizes, int n_in,
                              void* d_out, int out_size)
{
    const float* x  = (const float*)d_in[0];
    const float* w1 = (const float*)d_in[1];
    const float* b1 = (const float*)d_in[2];
    const float* w2 = (const float*)d_in[3];
    const float* b2 = (const float*)d_in[4];
    float* out = (float*)d_out;

    mlp_64t_kernel<<<B_DIM, 64>>>(x, w1, b1, w2, b2, out);
}

// round 17
// speedup vs baseline: 1.1646x; 1.1646x over previous
#include <cuda_runtime.h>

// R13 champion + one change: sparse GEMV2 loads are float2 per lane
// (32 lanes cover each 256B w2 row) instead of float4 per 16 lanes.
//   h = relu(x[b,:] @ w1[b,:,:] + b1[b,:])   (D=128 -> H=256)
//   out = h @ w2[b,:,:] + b2[b,:]            (H=256 -> C=64)
// w2 rows with h[j]==0 are never loaded (exact, ~50% skipped).
// Why: R13's sparse phase has only ~16 active loads/thread -> latency-bound
// (~2 DRAM round trips; isolated phase measured 61% DRAM in R12). float2
// lanes double the slot count to 64 (~32 active independent loads/thread),
// halving the latency-bound floor at identical bytes/coalescing. Predicate
// is now warp-uniform (all 32 lanes share row j): zero divergence.

#define B_DIM 4096
#define D_DIM 128
#define H_DIM 256
#define C_DIM 64

__global__ void __launch_bounds__(128, 10) mlp_mask_f2_kernel(
    const float* __restrict__ x,
    const float* __restrict__ w1,
    const float* __restrict__ b1,
    const float* __restrict__ w2,
    const float* __restrict__ b2,
    float* __restrict__ out)
{
    const int l = threadIdx.x;       // 0..127
    const int b = blockIdx.x;

    __shared__ float  x_s[D_DIM];
    __shared__ float  h_s[H_DIM];
    __shared__ float4 part[128];     // GEMV1 partials
    __shared__ float2 part2[128];    // GEMV2 partials

    // ---- stage x[b,:] ----
    x_s[l] = x[(size_t)b * D_DIM + l];
    __syncthreads();

    // ================= GEMV1: h[j] = sum_d x[d] * w1[d, j] =================
    // w1[b] as float4[128][64]. Thread: (dchunk = l>>6, g = l&63).
    // 64 float4 loads/thread, warp-contiguous 1024B rows. (Proven, unchanged.)
    {
        const float4* w1v = reinterpret_cast<const float4*>(
            w1 + (size_t)b * D_DIM * H_DIM);
        const int g     = l & 63;
        const int dbase = (l >> 6) * 64;

        float4 acc = make_float4(0.f, 0.f, 0.f, 0.f);
        #pragma unroll
        for (int i = 0; i < 64; ++i) {
            const int d = dbase + i;
            const float  xv = x_s[d];
            const float4 w  = __ldcs(&w1v[d * (H_DIM / 4) + g]);
            acc.x = fmaf(xv, w.x, acc.x);
            acc.y = fmaf(xv, w.y, acc.y);
            acc.z = fmaf(xv, w.z, acc.z);
            acc.w = fmaf(xv, w.w, acc.w);
        }
        part[l] = acc;
    }
    __syncthreads();

    // reduce 2 partials, add bias, ReLU -> h_s
    if (l < 64) {
        float4 s0 = part[l];
        float4 s1 = part[64 + l];
        float4 bb = reinterpret_cast<const float4*>(b1 + (size_t)b * H_DIM)[l];
        float4 h4;
        h4.x = fmaxf(s0.x + s1.x + bb.x, 0.f);
        h4.y = fmaxf(s0.y + s1.y + bb.y, 0.f);
        h4.z = fmaxf(s0.z + s1.z + bb.z, 0.f);
        h4.w = fmaxf(s0.w + s1.w + bb.w, 0.f);
        reinterpret_cast<float4*>(h_s)[l] = h4;
    }
    __syncthreads();

    // ========== GEMV2 (sparse, register-mask, float2 lanes): ===============
    // out[c] = sum_{j: h[j]>0} h[j] * w2[j, c]
    // w2[b] as float2[256][32]. Thread: (jslot = l>>5 in 0..3, lane = l&31).
    // Row j = jslot + 4*i (affine), i in 0..63 -> 64-bit register mask,
    // ~32 active independent 8B loads/thread; warp covers a full 256B row.
    {
        const float2* w2v = reinterpret_cast<const float2*>(
            w2 + (size_t)b * H_DIM * C_DIM);
        const int lane  = l & 31;
        const int jslot = l >> 5;

        // Phase 1: 64-bit activity mask (independent pipelined LDS reads).
        unsigned mLo = 0, mHi = 0;
        #pragma unroll
        for (int i = 0; i < 32; ++i) {
            mLo |= (h_s[jslot + 4 * i]        > 0.f) ? (1u << i) : 0u;
            mHi |= (h_s[jslot + 4 * (i + 32)] > 0.f) ? (1u << i) : 0u;
        }

        // Phase 2: predicated loads from register bits only -> batch freely.
        float2 acc = make_float2(0.f, 0.f);
        #pragma unroll
        for (int i = 0; i < 32; ++i) {
            if ((mLo >> i) & 1u) {
                const int j = jslot + 4 * i;
                const float2 wv = __ldcs(&w2v[j * (C_DIM / 2) + lane]);
                const float  hv = h_s[j];
                acc.x = fmaf(hv, wv.x, acc.x);
                acc.y = fmaf(hv, wv.y, acc.y);
            }
        }
        #pragma unroll
        for (int i = 0; i < 32; ++i) {
            if ((mHi >> i) & 1u) {
                const int j = jslot + 4 * (i + 32);
                const float2 wv = __ldcs(&w2v[j * (C_DIM / 2) + lane]);
                const float  hv = h_s[j];
                acc.x = fmaf(hv, wv.x, acc.x);
                acc.y = fmaf(hv, wv.y, acc.y);
            }
        }
        part2[l] = acc;   // index = jslot*32 + lane
    }
    __syncthreads();

    // reduce 4 jslot-partials per lane, add bias, streaming store
    if (l < 32) {
        float2 p0 = part2[l];
        float2 p1 = part2[32 + l];
        float2 p2 = part2[64 + l];
        float2 p3 = part2[96 + l];
        float2 bb = reinterpret_cast<const float2*>(b2 + (size_t)b * C_DIM)[l];
        float2 o;
        o.x = (p0.x + p1.x) + (p2.x + p3.x) + bb.x;
        o.y = (p0.y + p1.y) + (p2.y + p3.y) + bb.y;
        __stcs(reinterpret_cast<float2*>(out + (size_t)b * C_DIM) + l, o);
    }
}

extern "C" void kernel_launch(void* const* d_in, const int* in_sizes, int n_in,
                              void* d_out, int out_size)
{
    const float* x  = (const float*)d_in[0];
    const float* w1 = (const float*)d_in[1];
    const float* b1 = (const float*)d_in[2];
    const float* w2 = (const float*)d_in[3];
    const float* b2 = (const float*)d_in[4];
    float* out = (float*)d_out;

    mlp_mask_f2_kernel<<<B_DIM, 128>>>(x, w1, b1, w2, b2, out);
}